// round 14
// baseline (speedup 1.0000x reference)
#include <cuda_runtime.h>
#include <cuda_fp16.h>
#include <cstdint>

#define B_   4
#define S_   2048
#define F_   64
#define HID_ 256
#define D_   128
#define H_   8
#define DK_  16

typedef unsigned long long u64;
typedef unsigned int u32;
typedef unsigned short u16;

// fp16 operands for attention (dk-pair-permuted rows; Vt key-permuted):
//  g_qs/g_ks: [bh][s][16]  (Q pre-scaled by 0.25*log2e)
//  g_vt:      [bh][dk][s]
__device__ __align__(16) u16 g_qs[B_ * H_ * S_ * 16];
__device__ __align__(16) u16 g_ks[B_ * H_ * S_ * 16];
__device__ __align__(16) u16 g_vt[B_ * H_ * 16 * S_];
__device__ unsigned g_max[B_ * D_];
__device__ unsigned g_count;

// pair-adjacent packed weights (R11 layout):
//  g_w1p: [mlp][n=256][ks=4][tig=4][pair=2]   (3*8192 u32)
//  g_w2p: [mlp][n=128][ks=16][tig=4][pair=2]  (3*16384 u32)
__device__ __align__(16) u32 g_w1p[3 * 8192];
__device__ __align__(16) u32 g_w2p[3 * 16384];

// ---- order-preserving float <-> uint keys for atomicMax ----
__device__ __forceinline__ unsigned fkey(float f) {
    unsigned u = __float_as_uint(f);
    return (u & 0x80000000u) ? ~u : (u | 0x80000000u);
}
__device__ __forceinline__ float ikey(unsigned k) {
    unsigned u = (k & 0x80000000u) ? (k & 0x7FFFFFFFu) : ~k;
    return __uint_as_float(u);
}

// ---- fp16 pack: u32 = {lo16 = lo_val, hi16 = hi_val} ----
__device__ __forceinline__ u32 pkhf(float lo_val, float hi_val) {
    u32 d;
    asm("cvt.rn.f16x2.f32 %0, %1, %2;" : "=r"(d) : "f"(hi_val), "f"(lo_val));
    return d;
}
// ---- packed fp16 exp2 ----
__device__ __forceinline__ u32 ex2h2(u32 x) {
    u32 d;
    asm("ex2.approx.f16x2 %0, %1;" : "=r"(d) : "r"(x));
    return d;
}
// ---- cp.async 16B ----
__device__ __forceinline__ void cpa16(u32 saddr, const void* g) {
    asm volatile("cp.async.cg.shared.global [%0], [%1], 16;" :: "r"(saddr), "l"(g));
}
__device__ __forceinline__ void cpa_commit() {
    asm volatile("cp.async.commit_group;");
}
template <int N>
__device__ __forceinline__ void cpa_wait() {
    asm volatile("cp.async.wait_group %0;" :: "n"(N));
}

// ---- fp16 mma m16n8k16, fp32 D ----
__device__ __forceinline__ void mma_f16(float d[4], const u32 a[4], u32 b0, u32 b1) {
    asm volatile(
        "mma.sync.aligned.m16n8k16.row.col.f32.f16.f16.f32 "
        "{%0,%1,%2,%3}, {%4,%5,%6,%7}, {%8,%9}, {%0,%1,%2,%3};"
        : "+f"(d[0]), "+f"(d[1]), "+f"(d[2]), "+f"(d[3])
        : "r"(a[0]), "r"(a[1]), "r"(a[2]), "r"(a[3]), "r"(b0), "r"(b1));
}
// ---- fp16 mma m16n8k16, fp16 D, C = 0 ----
__device__ __forceinline__ void mma_f16d(u32& d0, u32& d1, const u32 a[4], u32 b0, u32 b1) {
    asm volatile(
        "mma.sync.aligned.m16n8k16.row.col.f16.f16.f16.f16 "
        "{%0,%1}, {%2,%3,%4,%5}, {%6,%7}, {%8,%8};"
        : "=r"(d0), "=r"(d1)
        : "r"(a[0]), "r"(a[1]), "r"(a[2]), "r"(a[3]), "r"(b0), "r"(b1), "r"(0u));
}

// dk-pair permutation for Q/K rows: logical pair t -> physical u32 slot
__device__ __forceinline__ int dk_pair_phys(int t) {
    return (t < 4) ? (2 * t) : (2 * (t - 4) + 1);
}
// key permutation within 16-key groups for Vt
__device__ __forceinline__ int v_key_phys(int m) {
    const int t = m >> 1, e = m & 1;
    return ((t < 4) ? (4 * t) : (4 * (t - 4) + 2)) + e;
}

// ============================================================
// Weight packer + g_max/g_count init (R11 version).
// ============================================================
__global__ void __launch_bounds__(256) pack_weights_kernel(
    const float* __restrict__ qW1, const float* __restrict__ kW1, const float* __restrict__ vW1,
    const float* __restrict__ qW2, const float* __restrict__ kW2, const float* __restrict__ vW2)
{
    const int i = blockIdx.x * 256 + threadIdx.x;
    if (i == 0) g_count = 0u;
    if (i < B_ * D_) g_max[i] = 0u;
    if (i < 3 * 8192) {
        const int mlp = i >> 13;
        const int r   = i & 8191;
        const int p   = r & 1;
        const int tig = (r >> 1) & 3;
        const int ks  = (r >> 3) & 3;
        const int n   = r >> 5;
        const float* W = (mlp == 0) ? qW1 : (mlp == 1) ? kW1 : vW1;
        const int kp = 8 * ks + tig + (p ? 4 : 0);
        g_w1p[i] = pkhf(W[(2 * kp) * HID_ + n], W[(2 * kp + 1) * HID_ + n]);
    }
    if (i < 3 * 16384) {
        const int mlp = i >> 14;
        const int r   = i & 16383;
        const int p   = r & 1;
        const int tig = (r >> 1) & 3;
        const int ks  = (r >> 3) & 15;
        const int n   = r >> 7;
        const float* W = (mlp == 0) ? qW2 : (mlp == 1) ? kW2 : vW2;
        const int kp = 8 * ks + tig + (p ? 4 : 0);
        g_w2p[i] = pkhf(W[(2 * kp) * D_ + n], W[(2 * kp + 1) * D_ + n]);
    }
}

// ============================================================
// Tensor-core MLP (R11 version): block = 64 tokens, 8 warps.
// grid (8192/64, 3). Weight fetch = LDG.64 (pair-adjacent).
// ============================================================
__global__ void __launch_bounds__(256) mlp_mma_kernel(
    const float* __restrict__ x,
    const float* __restrict__ qb1, const float* __restrict__ qb2,
    const float* __restrict__ kb1, const float* __restrict__ kb2,
    const float* __restrict__ vb1, const float* __restrict__ vb2)
{
    __shared__ u32 xs[64][36];
    __shared__ u32 hsm[64][132];

    const int tid  = threadIdx.x;
    const int lane = tid & 31;
    const int warp = tid >> 5;
    const int gID  = lane >> 2;
    const int tig  = lane & 3;
    const int mlp  = blockIdx.y;
    const int tok0 = blockIdx.x * 64;

    const float* b1v = (mlp == 0) ? qb1 : (mlp == 1) ? kb1 : vb1;
    const float* b2v = (mlp == 0) ? qb2 : (mlp == 1) ? kb2 : vb2;

    {
        const float4* xg = (const float4*)(x + (size_t)tok0 * F_);
        #pragma unroll
        for (int r = 0; r < 4; r++) {
            const int g   = tid + r * 256;
            const int tok = g >> 4;
            const int f4  = g & 15;
            const float4 v = xg[g];
            xs[tok][f4 * 2 + 0] = pkhf(v.x, v.y);
            xs[tok][f4 * 2 + 1] = pkhf(v.z, v.w);
        }
    }
    __syncthreads();

    const int tg = warp >> 1;
    const int nh = warp & 1;
    const int ra = tg * 16 + gID;

    // ---- Layer 1: 16 n-tiles x 4 k-steps ----
    float acc[16][4];
    #pragma unroll
    for (int j = 0; j < 16; j++)
        #pragma unroll
        for (int e = 0; e < 4; e++) acc[j][e] = 0.f;

    {
        const u32* wb = g_w1p + mlp * 8192;
        #pragma unroll
        for (int ks = 0; ks < 4; ks++) {
            u32 a[4];
            a[0] = xs[ra][8 * ks + tig];
            a[1] = xs[ra + 8][8 * ks + tig];
            a[2] = xs[ra][8 * ks + tig + 4];
            a[3] = xs[ra + 8][8 * ks + tig + 4];
            #pragma unroll
            for (int j = 0; j < 16; j++) {
                const int n = nh * 128 + j * 8 + gID;
                const uint2 w = __ldg((const uint2*)(wb + n * 32 + ks * 8 + tig * 2));
                mma_f16(acc[j], a, w.x, w.y);
            }
        }
    }

    #pragma unroll
    for (int j = 0; j < 16; j++) {
        const int c0 = nh * 128 + j * 8 + 2 * tig;
        const float bb0 = b1v[c0], bb1 = b1v[c0 + 1];
        float e0 = acc[j][0] + bb0, e1 = acc[j][1] + bb1;
        float e2 = acc[j][2] + bb0, e3 = acc[j][3] + bb1;
        e0 = (e0 > 0.f) ? e0 : (__expf(e0) - 1.f);
        e1 = (e1 > 0.f) ? e1 : (__expf(e1) - 1.f);
        e2 = (e2 > 0.f) ? e2 : (__expf(e2) - 1.f);
        e3 = (e3 > 0.f) ? e3 : (__expf(e3) - 1.f);
        hsm[ra][nh * 64 + 4 * j + tig]     = pkhf(e0, e1);
        hsm[ra + 8][nh * 64 + 4 * j + tig] = pkhf(e2, e3);
    }
    __syncthreads();

    // ---- Layer 2: 8 n-tiles x 16 k-steps ----
    float out[8][4];
    #pragma unroll
    for (int j = 0; j < 8; j++)
        #pragma unroll
        for (int e = 0; e < 4; e++) out[j][e] = 0.f;

    {
        const u32* wb = g_w2p + mlp * 16384;
        #pragma unroll
        for (int ks = 0; ks < 16; ks++) {
            u32 a[4];
            a[0] = hsm[ra][8 * ks + tig];
            a[1] = hsm[ra + 8][8 * ks + tig];
            a[2] = hsm[ra][8 * ks + tig + 4];
            a[3] = hsm[ra + 8][8 * ks + tig + 4];
            #pragma unroll
            for (int j = 0; j < 8; j++) {
                const int n = nh * 64 + j * 8 + gID;
                const uint2 w = __ldg((const uint2*)(wb + n * 128 + ks * 8 + tig * 2));
                mma_f16(out[j], a, w.x, w.y);
            }
        }
    }

    // ---- epilogue: bias, scale(Q), permuted scatter ----
    const float qsc = (mlp == 0) ? 0.25f * 1.4426950408889634f : 1.0f;
    #pragma unroll
    for (int j = 0; j < 8; j++) {
        const int c0 = nh * 64 + j * 8 + 2 * tig;
        const float bb0 = b2v[c0], bb1 = b2v[c0 + 1];
        const float v00 = (out[j][0] + bb0) * qsc;
        const float v01 = (out[j][1] + bb1) * qsc;
        const float v10 = (out[j][2] + bb0) * qsc;
        const float v11 = (out[j][3] + bb1) * qsc;
        const u32 pr = pkhf(v00, v01);
        const u32 ps = pkhf(v10, v11);

        const int h   = c0 >> 4;
        const int dk0 = c0 & 15;
        const int tokA = tok0 + ra;
        const int bA = tokA >> 11, sA = tokA & (S_ - 1);
        const int tokB = tokA + 8;
        const int bB = tokB >> 11, sB = tokB & (S_ - 1);
        const int bhA = bA * H_ + h, bhB = bB * H_ + h;

        if (mlp < 2) {
            u16* base = (mlp == 0) ? g_qs : g_ks;
            const int php = dk_pair_phys(dk0 >> 1);
            *(u32*)&base[((size_t)bhA * S_ + sA) * 16 + php * 2] = pr;
            *(u32*)&base[((size_t)bhB * S_ + sB) * 16 + php * 2] = ps;
        } else {
            const int spA = (sA & ~15) | v_key_phys(sA & 15);
            const int spB = (sB & ~15) | v_key_phys(sB & 15);
            g_vt[((size_t)bhA * 16 + dk0) * S_ + spA]     = (u16)(pr & 0xFFFF);
            g_vt[((size_t)bhA * 16 + dk0 + 1) * S_ + spA] = (u16)(pr >> 16);
            g_vt[((size_t)bhB * 16 + dk0) * S_ + spB]     = (u16)(ps & 0xFFFF);
            g_vt[((size_t)bhB * 16 + dk0 + 1) * S_ + spB] = (u16)(ps >> 16);
        }
    }
}

#define QSTR 16
#define VSTR 144
#define ONES 0x3C003C00u
#define QT   128                       // queries per attention block
#define NBLK ((S_ / QT) * B_ * H_)     // 512
#define NT   (S_ / 128)

// ============================================================
// fp16 mma.sync flash attention; 128 q/block (8 warps x 16 rows),
// LDS.64 frags; cp.async double-buffered K/V shared by all 8 warps.
// grid (S/128, B*H), 256 threads.
// ============================================================
__global__ void __launch_bounds__(256) attn_mma_kernel(float* __restrict__ outp)
{
    __shared__ __align__(16) u16 Qs[128][QSTR];         // 4096 B
    __shared__ __align__(16) u16 Ks[2][128][QSTR];      // 8192 B
    __shared__ __align__(16) u16 Vt[2][16][VSTR];       // 9216 B
    __shared__ float red[128 * 17];                     // 8704 B
    __shared__ unsigned s_last;

    const int tid  = threadIdx.x;
    const int lane = tid & 31;
    const int warp = tid >> 5;
    const int gID  = lane >> 2;
    const int tig  = lane & 3;
    const int bh   = blockIdx.y;
    const int q0   = blockIdx.x * QT;

    {
        const int r    = tid >> 1;
        const int part = tid & 1;
        const uint4 v = *(const uint4*)&g_qs[((size_t)bh * S_ + q0 + r) * 16 + part * 8];
        *(uint4*)&Qs[r][part * 8] = v;
    }
    __syncthreads();

    u32 qa[4];
    const int ra = warp * 16 + gID;
    {
        const uint2 qA = *(const uint2*)&Qs[ra][4 * tig];
        const uint2 qB = *(const uint2*)&Qs[ra + 8][4 * tig];
        qa[0] = qA.x; qa[2] = qA.y;
        qa[1] = qB.x; qa[3] = qB.y;
    }

    // per-thread cp.async coordinates: one 16B chunk each for K and Vt
    const int kr = tid >> 1;
    const int kp = (tid & 1) * 8;
    const int vd = tid >> 4;
    const int vo = (tid & 15) * 8;
    const u16* kgb = g_ks + (size_t)bh * S_ * 16;
    const u16* vgb = g_vt + (size_t)bh * 16 * S_;

    const u32 sKa = (u32)__cvta_generic_to_shared(&Ks[0][kr][kp]);
    const u32 sVa = (u32)__cvta_generic_to_shared(&Vt[0][vd][vo]);
    const u32 kBufB = 128 * QSTR * 2;   // bytes per K buffer
    const u32 vBufB = 16 * VSTR * 2;    // bytes per Vt buffer

    // prefetch tile 0 into buffer 0
    {
        cpa16(sKa, &kgb[(size_t)kr * 16 + kp]);
        cpa16(sVa, &vgb[(size_t)vd * S_ + vo]);
        cpa_commit();
    }

    float out0[4] = {0.f, 0.f, 0.f, 0.f};
    float out1[4] = {0.f, 0.f, 0.f, 0.f};
    float ls[4]   = {0.f, 0.f, 0.f, 0.f};

    for (int t = 0; t < NT; t++) {
        const int buf = t & 1;
        if (t + 1 < NT) {
            const int nb = (t + 1) & 1;
            const int tt = (t + 1) * 128;
            cpa16(sKa + nb * kBufB, &kgb[(size_t)(tt + kr) * 16 + kp]);
            cpa16(sVa + nb * vBufB, &vgb[(size_t)vd * S_ + tt + vo]);
            cpa_commit();
            cpa_wait<1>();
        } else {
            cpa_wait<0>();
        }
        __syncthreads();

        #pragma unroll
        for (int half = 0; half < 2; half++) {
            u32 pa[8], pb[8];

            #pragma unroll
            for (int j = 0; j < 8; j++) {
                const int kn = half * 64 + j * 8 + gID;
                const uint2 bb = *(const uint2*)&Ks[buf][kn][4 * tig];
                u32 d0, d1;
                mma_f16d(d0, d1, qa, bb.x, bb.y);
                pa[j] = ex2h2(d0);
                pb[j] = ex2h2(d1);
            }

            #pragma unroll
            for (int ks = 0; ks < 4; ks++) {
                const u32 A[4] = {pa[2 * ks], pb[2 * ks], pa[2 * ks + 1], pb[2 * ks + 1]};
                const int kb2 = half * 64 + ks * 16 + 4 * tig;
                {
                    const uint2 vv = *(const uint2*)&Vt[buf][gID][kb2];
                    mma_f16(out0, A, vv.x, vv.y);
                }
                {
                    const uint2 vv = *(const uint2*)&Vt[buf][8 + gID][kb2];
                    mma_f16(out1, A, vv.x, vv.y);
                }
                mma_f16(ls, A, ONES, ONES);
            }
        }
        __syncthreads();   // all reads of buf done before it is refilled at t+2
    }

    const float i0 = 1.f / ls[0];
    const float i1 = 1.f / ls[2];

    {
        const int c0 = 2 * tig;
        red[ra * 17 + c0 + 0]       = out0[0] * i0;
        red[ra * 17 + c0 + 1]       = out0[1] * i0;
        red[(ra + 8) * 17 + c0 + 0] = out0[2] * i1;
        red[(ra + 8) * 17 + c0 + 1] = out0[3] * i1;
        red[ra * 17 + 8 + c0 + 0]       = out1[0] * i0;
        red[ra * 17 + 8 + c0 + 1]       = out1[1] * i0;
        red[(ra + 8) * 17 + 8 + c0 + 0] = out1[2] * i1;
        red[(ra + 8) * 17 + 8 + c0 + 1] = out1[3] * i1;
    }
    __syncthreads();

    float* part = (float*)&Qs[0][0];   // [16][16] scratch
    {
        const int c  = tid & 15;
        const int r0 = tid >> 4;       // 0..15
        float m = red[r0 * 17 + c];
        #pragma unroll
        for (int i = 1; i < 8; i++)
            m = fmaxf(m, red[(r0 + 16 * i) * 17 + c]);
        part[r0 * 16 + c] = m;
    }
    __syncthreads();
    if (tid < 16) {
        float m = part[tid];
        #pragma unroll
        for (int r = 1; r < 16; r++)
            m = fmaxf(m, part[r * 16 + tid]);
        const int b = bh >> 3, h = bh & 7;
        atomicMax(&g_max[b * D_ + h * DK_ + tid], fkey(m));
    }

    // ---- last block writes the output ----
    __threadfence();
    __syncthreads();
    if (tid == 0) s_last = atomicAdd(&g_count, 1u);
    __syncthreads();
    if (s_last == NBLK - 1) {
        #pragma unroll
        for (int r = 0; r < 2; r++) {
            const int i = tid + r * 256;
            outp[i] = ikey(atomicOr(&g_max[i], 0u));
        }
    }
}

extern "C" void kernel_launch(void* const* d_in, const int* in_sizes, int n_in,
                              void* d_out, int out_size)
{
    const float* x   = (const float*)d_in[0];
    const float* qW1 = (const float*)d_in[1];
    const float* qb1 = (const float*)d_in[2];
    const float* qW2 = (const float*)d_in[3];
    const float* qb2 = (const float*)d_in[4];
    const float* kW1 = (const float*)d_in[5];
    const float* kb1 = (const float*)d_in[6];
    const float* kW2 = (const float*)d_in[7];
    const float* kb2 = (const float*)d_in[8];
    const float* vW1 = (const float*)d_in[9];
    const float* vb1 = (const float*)d_in[10];
    const float* vW2 = (const float*)d_in[11];
    const float* vb2 = (const float*)d_in[12];

    pack_weights_kernel<<<192, 256>>>(qW1, kW1, vW1, qW2, kW2, vW2);

    dim3 gmlp(B_ * S_ / 64, 3);
    mlp_mma_kernel<<<gmlp, 256>>>(x, qb1, qb2, kb1, kb2, vb1, vb2);

    dim3 gatt(S_ / QT, B_ * H_);
    attn_mma_kernel<<<gatt, 256>>>((float*)d_out);
}

// round 15
// speedup vs baseline: 1.0324x; 1.0324x over previous
#include <cuda_runtime.h>
#include <cuda_fp16.h>
#include <cstdint>

#define B_   4
#define S_   2048
#define F_   64
#define HID_ 256
#define D_   128
#define H_   8
#define DK_  16

typedef unsigned long long u64;
typedef unsigned int u32;
typedef unsigned short u16;

// fp16 operands for attention (dk-pair-permuted rows; Vt key-permuted):
//  g_qs/g_ks: [bh][s][16]  (Q pre-scaled by 0.25*log2e)
//  g_vt:      [bh][dk][s]
__device__ __align__(16) u16 g_qs[B_ * H_ * S_ * 16];
__device__ __align__(16) u16 g_ks[B_ * H_ * S_ * 16];
__device__ __align__(16) u16 g_vt[B_ * H_ * 16 * S_];
__device__ unsigned g_max[B_ * D_];
__device__ unsigned g_count;

// pair-adjacent packed weights (R11 layout):
//  g_w1p: [mlp][n=256][ks=4][tig=4][pair=2]   (3*8192 u32)
//  g_w2p: [mlp][n=128][ks=16][tig=4][pair=2]  (3*16384 u32)
__device__ __align__(16) u32 g_w1p[3 * 8192];
__device__ __align__(16) u32 g_w2p[3 * 16384];

// ---- order-preserving float <-> uint keys for atomicMax ----
__device__ __forceinline__ unsigned fkey(float f) {
    unsigned u = __float_as_uint(f);
    return (u & 0x80000000u) ? ~u : (u | 0x80000000u);
}
__device__ __forceinline__ float ikey(unsigned k) {
    unsigned u = (k & 0x80000000u) ? (k & 0x7FFFFFFFu) : ~k;
    return __uint_as_float(u);
}

// ---- fp16 pack: u32 = {lo16 = lo_val, hi16 = hi_val} ----
__device__ __forceinline__ u32 pkhf(float lo_val, float hi_val) {
    u32 d;
    asm("cvt.rn.f16x2.f32 %0, %1, %2;" : "=r"(d) : "f"(hi_val), "f"(lo_val));
    return d;
}
// ---- packed fp16 exp2 ----
__device__ __forceinline__ u32 ex2h2(u32 x) {
    u32 d;
    asm("ex2.approx.f16x2 %0, %1;" : "=r"(d) : "r"(x));
    return d;
}
// ---- cp.async 16B ----
__device__ __forceinline__ void cpa16(u32 saddr, const void* g) {
    asm volatile("cp.async.cg.shared.global [%0], [%1], 16;" :: "r"(saddr), "l"(g));
}
__device__ __forceinline__ void cpa_commit() {
    asm volatile("cp.async.commit_group;");
}
template <int N>
__device__ __forceinline__ void cpa_wait() {
    asm volatile("cp.async.wait_group %0;" :: "n"(N));
}

// ---- fp16 mma m16n8k16, fp32 D ----
__device__ __forceinline__ void mma_f16(float d[4], const u32 a[4], u32 b0, u32 b1) {
    asm volatile(
        "mma.sync.aligned.m16n8k16.row.col.f32.f16.f16.f32 "
        "{%0,%1,%2,%3}, {%4,%5,%6,%7}, {%8,%9}, {%0,%1,%2,%3};"
        : "+f"(d[0]), "+f"(d[1]), "+f"(d[2]), "+f"(d[3])
        : "r"(a[0]), "r"(a[1]), "r"(a[2]), "r"(a[3]), "r"(b0), "r"(b1));
}
// ---- fp16 mma m16n8k16, fp16 D, C = 0 ----
__device__ __forceinline__ void mma_f16d(u32& d0, u32& d1, const u32 a[4], u32 b0, u32 b1) {
    asm volatile(
        "mma.sync.aligned.m16n8k16.row.col.f16.f16.f16.f16 "
        "{%0,%1}, {%2,%3,%4,%5}, {%6,%7}, {%8,%8};"
        : "=r"(d0), "=r"(d1)
        : "r"(a[0]), "r"(a[1]), "r"(a[2]), "r"(a[3]), "r"(b0), "r"(b1), "r"(0u));
}

// dk-pair permutation for Q/K rows: logical pair t -> physical u32 slot
__device__ __forceinline__ int dk_pair_phys(int t) {
    return (t < 4) ? (2 * t) : (2 * (t - 4) + 1);
}
// key permutation within 16-key groups for Vt
__device__ __forceinline__ int v_key_phys(int m) {
    const int t = m >> 1, e = m & 1;
    return ((t < 4) ? (4 * t) : (4 * (t - 4) + 2)) + e;
}

// ============================================================
// Weight packer (coalesced reads: n in low bits) + init.
// ============================================================
__global__ void __launch_bounds__(256) pack_weights_kernel(
    const float* __restrict__ qW1, const float* __restrict__ kW1, const float* __restrict__ vW1,
    const float* __restrict__ qW2, const float* __restrict__ kW2, const float* __restrict__ vW2)
{
    const int i = blockIdx.x * 256 + threadIdx.x;
    if (i == 0) g_count = 0u;
    if (i < B_ * D_) g_max[i] = 0u;

    if (i < 3 * 8192) {   // W1: n in low 8 bits -> coalesced LDG
        const int n   = i & 255;
        const int r2  = i >> 8;            // 0..95
        const int p   = r2 & 1;
        const int tig = (r2 >> 1) & 3;
        const int ks  = (r2 >> 3) & 3;
        const int mlp = r2 >> 5;
        const float* W = (mlp == 0) ? qW1 : (mlp == 1) ? kW1 : vW1;
        const int kp = 8 * ks + tig + (p ? 4 : 0);
        // R11 output layout: [mlp][n][ks][tig][pair]
        const int out = ((mlp * 256 + n) * 4 + ks) * 8 + tig * 2 + p;
        g_w1p[out] = pkhf(W[(2 * kp) * HID_ + n], W[(2 * kp + 1) * HID_ + n]);
    }
    if (i < 3 * 16384) {  // W2: n in low 7 bits -> coalesced LDG
        const int n   = i & 127;
        const int r2  = i >> 7;            // 0..383
        const int p   = r2 & 1;
        const int tig = (r2 >> 1) & 3;
        const int ks  = (r2 >> 3) & 15;
        const int mlp = r2 >> 7;
        const float* W = (mlp == 0) ? qW2 : (mlp == 1) ? kW2 : vW2;
        const int kp = 8 * ks + tig + (p ? 4 : 0);
        // R11 output layout: [mlp][n][ks][tig][pair]
        const int out = ((mlp * 128 + n) * 16 + ks) * 8 + tig * 2 + p;
        g_w2p[out] = pkhf(W[(2 * kp) * D_ + n], W[(2 * kp + 1) * D_ + n]);
    }
}

// ============================================================
// Tensor-core MLP (R11 version): block = 64 tokens, 8 warps.
// grid (8192/64, 3). Weight fetch = LDG.64 (pair-adjacent).
// ============================================================
__global__ void __launch_bounds__(256) mlp_mma_kernel(
    const float* __restrict__ x,
    const float* __restrict__ qb1, const float* __restrict__ qb2,
    const float* __restrict__ kb1, const float* __restrict__ kb2,
    const float* __restrict__ vb1, const float* __restrict__ vb2)
{
    __shared__ u32 xs[64][36];
    __shared__ u32 hsm[64][132];

    const int tid  = threadIdx.x;
    const int lane = tid & 31;
    const int warp = tid >> 5;
    const int gID  = lane >> 2;
    const int tig  = lane & 3;
    const int mlp  = blockIdx.y;
    const int tok0 = blockIdx.x * 64;

    const float* b1v = (mlp == 0) ? qb1 : (mlp == 1) ? kb1 : vb1;
    const float* b2v = (mlp == 0) ? qb2 : (mlp == 1) ? kb2 : vb2;

    {
        const float4* xg = (const float4*)(x + (size_t)tok0 * F_);
        #pragma unroll
        for (int r = 0; r < 4; r++) {
            const int g   = tid + r * 256;
            const int tok = g >> 4;
            const int f4  = g & 15;
            const float4 v = xg[g];
            xs[tok][f4 * 2 + 0] = pkhf(v.x, v.y);
            xs[tok][f4 * 2 + 1] = pkhf(v.z, v.w);
        }
    }
    __syncthreads();

    const int tg = warp >> 1;
    const int nh = warp & 1;
    const int ra = tg * 16 + gID;

    // ---- Layer 1: 16 n-tiles x 4 k-steps ----
    float acc[16][4];
    #pragma unroll
    for (int j = 0; j < 16; j++)
        #pragma unroll
        for (int e = 0; e < 4; e++) acc[j][e] = 0.f;

    {
        const u32* wb = g_w1p + mlp * 8192;
        #pragma unroll
        for (int ks = 0; ks < 4; ks++) {
            u32 a[4];
            a[0] = xs[ra][8 * ks + tig];
            a[1] = xs[ra + 8][8 * ks + tig];
            a[2] = xs[ra][8 * ks + tig + 4];
            a[3] = xs[ra + 8][8 * ks + tig + 4];
            #pragma unroll
            for (int j = 0; j < 16; j++) {
                const int n = nh * 128 + j * 8 + gID;
                const uint2 w = __ldg((const uint2*)(wb + n * 32 + ks * 8 + tig * 2));
                mma_f16(acc[j], a, w.x, w.y);
            }
        }
    }

    #pragma unroll
    for (int j = 0; j < 16; j++) {
        const int c0 = nh * 128 + j * 8 + 2 * tig;
        const float bb0 = b1v[c0], bb1 = b1v[c0 + 1];
        float e0 = acc[j][0] + bb0, e1 = acc[j][1] + bb1;
        float e2 = acc[j][2] + bb0, e3 = acc[j][3] + bb1;
        e0 = (e0 > 0.f) ? e0 : (__expf(e0) - 1.f);
        e1 = (e1 > 0.f) ? e1 : (__expf(e1) - 1.f);
        e2 = (e2 > 0.f) ? e2 : (__expf(e2) - 1.f);
        e3 = (e3 > 0.f) ? e3 : (__expf(e3) - 1.f);
        hsm[ra][nh * 64 + 4 * j + tig]     = pkhf(e0, e1);
        hsm[ra + 8][nh * 64 + 4 * j + tig] = pkhf(e2, e3);
    }
    __syncthreads();

    // ---- Layer 2: 8 n-tiles x 16 k-steps ----
    float out[8][4];
    #pragma unroll
    for (int j = 0; j < 8; j++)
        #pragma unroll
        for (int e = 0; e < 4; e++) out[j][e] = 0.f;

    {
        const u32* wb = g_w2p + mlp * 16384;
        #pragma unroll
        for (int ks = 0; ks < 16; ks++) {
            u32 a[4];
            a[0] = hsm[ra][8 * ks + tig];
            a[1] = hsm[ra + 8][8 * ks + tig];
            a[2] = hsm[ra][8 * ks + tig + 4];
            a[3] = hsm[ra + 8][8 * ks + tig + 4];
            #pragma unroll
            for (int j = 0; j < 8; j++) {
                const int n = nh * 64 + j * 8 + gID;
                const uint2 w = __ldg((const uint2*)(wb + n * 128 + ks * 8 + tig * 2));
                mma_f16(out[j], a, w.x, w.y);
            }
        }
    }

    // ---- epilogue: bias, scale(Q), permuted scatter ----
    const float qsc = (mlp == 0) ? 0.25f * 1.4426950408889634f : 1.0f;
    #pragma unroll
    for (int j = 0; j < 8; j++) {
        const int c0 = nh * 64 + j * 8 + 2 * tig;
        const float bb0 = b2v[c0], bb1 = b2v[c0 + 1];
        const float v00 = (out[j][0] + bb0) * qsc;
        const float v01 = (out[j][1] + bb1) * qsc;
        const float v10 = (out[j][2] + bb0) * qsc;
        const float v11 = (out[j][3] + bb1) * qsc;
        const u32 pr = pkhf(v00, v01);
        const u32 ps = pkhf(v10, v11);

        const int h   = c0 >> 4;
        const int dk0 = c0 & 15;
        const int tokA = tok0 + ra;
        const int bA = tokA >> 11, sA = tokA & (S_ - 1);
        const int tokB = tokA + 8;
        const int bB = tokB >> 11, sB = tokB & (S_ - 1);
        const int bhA = bA * H_ + h, bhB = bB * H_ + h;

        if (mlp < 2) {
            u16* base = (mlp == 0) ? g_qs : g_ks;
            const int php = dk_pair_phys(dk0 >> 1);
            *(u32*)&base[((size_t)bhA * S_ + sA) * 16 + php * 2] = pr;
            *(u32*)&base[((size_t)bhB * S_ + sB) * 16 + php * 2] = ps;
        } else {
            const int spA = (sA & ~15) | v_key_phys(sA & 15);
            const int spB = (sB & ~15) | v_key_phys(sB & 15);
            g_vt[((size_t)bhA * 16 + dk0) * S_ + spA]     = (u16)(pr & 0xFFFF);
            g_vt[((size_t)bhA * 16 + dk0 + 1) * S_ + spA] = (u16)(pr >> 16);
            g_vt[((size_t)bhB * 16 + dk0) * S_ + spB]     = (u16)(ps & 0xFFFF);
            g_vt[((size_t)bhB * 16 + dk0 + 1) * S_ + spB] = (u16)(ps >> 16);
        }
    }
}

#define QSTR 16
#define VSTR 144
#define ONES 0x3C003C00u
#define NBLK ((S_ / 64) * B_ * H_)
#define NT   (S_ / 128)

// ============================================================
// fp16 mma.sync flash attention; LDS.64 frags; cp.async TRIPLE-buffered
// K/V -> single __syncthreads per tile. grid (S/64, B*H), 128 threads.
// ============================================================
__global__ void __launch_bounds__(128) attn_mma_kernel(float* __restrict__ outp)
{
    __shared__ __align__(16) u16 Qs[64][QSTR];          // 2048 B
    __shared__ __align__(16) u16 Ks[3][128][QSTR];      // 12288 B
    __shared__ __align__(16) u16 Vt[3][16][VSTR];       // 13824 B
    __shared__ float red[64 * 17];                      // 4352 B
    __shared__ unsigned s_last;

    const int tid  = threadIdx.x;
    const int lane = tid & 31;
    const int warp = tid >> 5;
    const int gID  = lane >> 2;
    const int tig  = lane & 3;
    const int bh   = blockIdx.y;
    const int q0   = blockIdx.x * 64;

    {
        const int r    = tid >> 1;
        const int part = tid & 1;
        const uint4 v = *(const uint4*)&g_qs[((size_t)bh * S_ + q0 + r) * 16 + part * 8];
        *(uint4*)&Qs[r][part * 8] = v;
    }
    __syncthreads();

    u32 qa[4];
    const int ra = warp * 16 + gID;
    {
        const uint2 qA = *(const uint2*)&Qs[ra][4 * tig];
        const uint2 qB = *(const uint2*)&Qs[ra + 8][4 * tig];
        qa[0] = qA.x; qa[2] = qA.y;
        qa[1] = qB.x; qa[3] = qB.y;
    }

    // per-thread cp.async coordinates (invariant across tiles)
    const int kr0 = tid >> 1;
    const int kp0 = (tid & 1) * 8;
    const int kr1 = (tid + 128) >> 1;
    const int kp1 = ((tid + 128) & 1) * 8;
    const int vd0 = tid >> 4;
    const int vo0 = (tid & 15) * 8;
    const int vd1 = (tid + 128) >> 4;
    const int vo1 = ((tid + 128) & 15) * 8;
    const u16* kgb = g_ks + (size_t)bh * S_ * 16;
    const u16* vgb = g_vt + (size_t)bh * 16 * S_;

    const u32 sKa0 = (u32)__cvta_generic_to_shared(&Ks[0][kr0][kp0]);
    const u32 sKa1 = (u32)__cvta_generic_to_shared(&Ks[0][kr1][kp1]);
    const u32 sVa0 = (u32)__cvta_generic_to_shared(&Vt[0][vd0][vo0]);
    const u32 sVa1 = (u32)__cvta_generic_to_shared(&Vt[0][vd1][vo1]);
    const u32 kBufB = 128 * QSTR * 2;   // bytes per K buffer
    const u32 vBufB = 16 * VSTR * 2;    // bytes per Vt buffer

    // prefetch tile 0 into buffer 0
    {
        cpa16(sKa0, &kgb[(size_t)kr0 * 16 + kp0]);
        cpa16(sKa1, &kgb[(size_t)kr1 * 16 + kp1]);
        cpa16(sVa0, &vgb[(size_t)vd0 * S_ + vo0]);
        cpa16(sVa1, &vgb[(size_t)vd1 * S_ + vo1]);
        cpa_commit();
    }

    float out0[4] = {0.f, 0.f, 0.f, 0.f};
    float out1[4] = {0.f, 0.f, 0.f, 0.f};
    float ls[4]   = {0.f, 0.f, 0.f, 0.f};

    int buf = 0;
    for (int t = 0; t < NT; t++) {
        if (t + 1 < NT) {   // prefetch next tile into buffer (t+1)%3
            const int nb = (buf == 2) ? 0 : buf + 1;
            const int tt = (t + 1) * 128;
            cpa16(sKa0 + nb * kBufB, &kgb[(size_t)(tt + kr0) * 16 + kp0]);
            cpa16(sKa1 + nb * kBufB, &kgb[(size_t)(tt + kr1) * 16 + kp1]);
            cpa16(sVa0 + nb * vBufB, &vgb[(size_t)vd0 * S_ + tt + vo0]);
            cpa16(sVa1 + nb * vBufB, &vgb[(size_t)vd1 * S_ + tt + vo1]);
            cpa_commit();
            cpa_wait<1>();   // tile t's group complete
        } else {
            cpa_wait<0>();
        }
        __syncthreads();     // single barrier per tile (3 buffers make the
                             // end-of-loop barrier redundant: buffer (t+1)%3
                             // was last read at t-2, two barriers ago)

        #pragma unroll
        for (int half = 0; half < 2; half++) {
            u32 pa[8], pb[8];

            #pragma unroll
            for (int j = 0; j < 8; j++) {
                const int kn = half * 64 + j * 8 + gID;
                const uint2 bb = *(const uint2*)&Ks[buf][kn][4 * tig];
                u32 d0, d1;
                mma_f16d(d0, d1, qa, bb.x, bb.y);
                pa[j] = ex2h2(d0);
                pb[j] = ex2h2(d1);
            }

            #pragma unroll
            for (int ks = 0; ks < 4; ks++) {
                const u32 A[4] = {pa[2 * ks], pb[2 * ks], pa[2 * ks + 1], pb[2 * ks + 1]};
                const int kb2 = half * 64 + ks * 16 + 4 * tig;
                {
                    const uint2 vv = *(const uint2*)&Vt[buf][gID][kb2];
                    mma_f16(out0, A, vv.x, vv.y);
                }
                {
                    const uint2 vv = *(const uint2*)&Vt[buf][8 + gID][kb2];
                    mma_f16(out1, A, vv.x, vv.y);
                }
                mma_f16(ls, A, ONES, ONES);
            }
        }
        buf = (buf == 2) ? 0 : buf + 1;
    }

    const float i0 = 1.f / ls[0];
    const float i1 = 1.f / ls[2];

    __syncthreads();   // all warps done with smem tiles before red reuse below
    {
        const int c0 = 2 * tig;
        red[ra * 17 + c0 + 0]       = out0[0] * i0;
        red[ra * 17 + c0 + 1]       = out0[1] * i0;
        red[(ra + 8) * 17 + c0 + 0] = out0[2] * i1;
        red[(ra + 8) * 17 + c0 + 1] = out0[3] * i1;
        red[ra * 17 + 8 + c0 + 0]       = out1[0] * i0;
        red[ra * 17 + 8 + c0 + 1]       = out1[1] * i0;
        red[(ra + 8) * 17 + 8 + c0 + 0] = out1[2] * i1;
        red[(ra + 8) * 17 + 8 + c0 + 1] = out1[3] * i1;
    }
    __syncthreads();

    float* part = (float*)&Qs[0][0];
    {
        const int c  = tid & 15;
        const int r0 = tid >> 4;
        float m = red[r0 * 17 + c];
        #pragma unroll
        for (int i = 1; i < 8; i++)
            m = fmaxf(m, red[(r0 + 8 * i) * 17 + c]);
        part[r0 * 16 + c] = m;
    }
    __syncthreads();
    if (tid < 16) {
        float m = part[tid];
        #pragma unroll
        for (int r = 1; r < 8; r++)
            m = fmaxf(m, part[r * 16 + tid]);
        const int b = bh >> 3, h = bh & 7;
        atomicMax(&g_max[b * D_ + h * DK_ + tid], fkey(m));
    }

    // ---- last block writes the output ----
    __threadfence();
    __syncthreads();
    if (tid == 0) s_last = atomicAdd(&g_count, 1u);
    __syncthreads();
    if (s_last == NBLK - 1) {
        #pragma unroll
        for (int r = 0; r < 4; r++) {
            const int i = tid + r * 128;
            outp[i] = ikey(atomicOr(&g_max[i], 0u));
        }
    }
}

extern "C" void kernel_launch(void* const* d_in, const int* in_sizes, int n_in,
                              void* d_out, int out_size)
{
    const float* x   = (const float*)d_in[0];
    const float* qW1 = (const float*)d_in[1];
    const float* qb1 = (const float*)d_in[2];
    const float* qW2 = (const float*)d_in[3];
    const float* qb2 = (const float*)d_in[4];
    const float* kW1 = (const float*)d_in[5];
    const float* kb1 = (const float*)d_in[6];
    const float* kW2 = (const float*)d_in[7];
    const float* kb2 = (const float*)d_in[8];
    const float* vW1 = (const float*)d_in[9];
    const float* vb1 = (const float*)d_in[10];
    const float* vW2 = (const float*)d_in[11];
    const float* vb2 = (const float*)d_in[12];

    pack_weights_kernel<<<192, 256>>>(qW1, kW1, vW1, qW2, kW2, vW2);

    dim3 gmlp(B_ * S_ / 64, 3);
    mlp_mma_kernel<<<gmlp, 256>>>(x, qb1, qb2, kb1, kb2, vb1, vb2);

    dim3 gatt(S_ / 64, B_ * H_);
    attn_mma_kernel<<<gatt, 128>>>((float*)d_out);
}

// round 16
// speedup vs baseline: 1.0360x; 1.0035x over previous
#include <cuda_runtime.h>
#include <cuda_fp16.h>
#include <cstdint>

#define B_   4
#define S_   2048
#define F_   64
#define HID_ 256
#define D_   128
#define H_   8
#define DK_  16

typedef unsigned long long u64;
typedef unsigned int u32;
typedef unsigned short u16;

// fp16 operands for attention (dk-pair-permuted rows; Vt key-permuted):
//  g_qs/g_ks: [bh][s][16]  (Q pre-scaled by 0.25*log2e)
//  g_vt:      [bh][dk][s]
__device__ __align__(16) u16 g_qs[B_ * H_ * S_ * 16];
__device__ __align__(16) u16 g_ks[B_ * H_ * S_ * 16];
__device__ __align__(16) u16 g_vt[B_ * H_ * 16 * S_];
__device__ unsigned g_max[B_ * D_];
__device__ unsigned g_count;

// pair-adjacent packed weights (R11 layout):
//  g_w1p: [mlp][n=256][ks=4][tig=4][pair=2]   (3*8192 u32)
//  g_w2p: [mlp][n=128][ks=16][tig=4][pair=2]  (3*16384 u32)
__device__ __align__(16) u32 g_w1p[3 * 8192];
__device__ __align__(16) u32 g_w2p[3 * 16384];

// ---- order-preserving float <-> uint keys for atomicMax ----
__device__ __forceinline__ unsigned fkey(float f) {
    unsigned u = __float_as_uint(f);
    return (u & 0x80000000u) ? ~u : (u | 0x80000000u);
}
__device__ __forceinline__ float ikey(unsigned k) {
    unsigned u = (k & 0x80000000u) ? (k & 0x7FFFFFFFu) : ~k;
    return __uint_as_float(u);
}

// ---- fp16 pack: u32 = {lo16 = lo_val, hi16 = hi_val} ----
__device__ __forceinline__ u32 pkhf(float lo_val, float hi_val) {
    u32 d;
    asm("cvt.rn.f16x2.f32 %0, %1, %2;" : "=r"(d) : "f"(hi_val), "f"(lo_val));
    return d;
}
// ---- packed fp16 exp2 ----
__device__ __forceinline__ u32 ex2h2(u32 x) {
    u32 d;
    asm("ex2.approx.f16x2 %0, %1;" : "=r"(d) : "r"(x));
    return d;
}
// ---- cp.async 16B ----
__device__ __forceinline__ void cpa16(u32 saddr, const void* g) {
    asm volatile("cp.async.cg.shared.global [%0], [%1], 16;" :: "r"(saddr), "l"(g));
}
__device__ __forceinline__ void cpa_commit() {
    asm volatile("cp.async.commit_group;");
}
template <int N>
__device__ __forceinline__ void cpa_wait() {
    asm volatile("cp.async.wait_group %0;" :: "n"(N));
}

// ---- fp16 mma m16n8k16, fp32 D ----
__device__ __forceinline__ void mma_f16(float d[4], const u32 a[4], u32 b0, u32 b1) {
    asm volatile(
        "mma.sync.aligned.m16n8k16.row.col.f32.f16.f16.f32 "
        "{%0,%1,%2,%3}, {%4,%5,%6,%7}, {%8,%9}, {%0,%1,%2,%3};"
        : "+f"(d[0]), "+f"(d[1]), "+f"(d[2]), "+f"(d[3])
        : "r"(a[0]), "r"(a[1]), "r"(a[2]), "r"(a[3]), "r"(b0), "r"(b1));
}
// ---- fp16 mma m16n8k16, fp16 D, C = 0 ----
__device__ __forceinline__ void mma_f16d(u32& d0, u32& d1, const u32 a[4], u32 b0, u32 b1) {
    asm volatile(
        "mma.sync.aligned.m16n8k16.row.col.f16.f16.f16.f16 "
        "{%0,%1}, {%2,%3,%4,%5}, {%6,%7}, {%8,%8};"
        : "=r"(d0), "=r"(d1)
        : "r"(a[0]), "r"(a[1]), "r"(a[2]), "r"(a[3]), "r"(b0), "r"(b1), "r"(0u));
}

// dk-pair permutation for Q/K rows: logical pair t -> physical u32 slot
__device__ __forceinline__ int dk_pair_phys(int t) {
    return (t < 4) ? (2 * t) : (2 * (t - 4) + 1);
}
// key permutation within 16-key groups for Vt
__device__ __forceinline__ int v_key_phys(int m) {
    const int t = m >> 1, e = m & 1;
    return ((t < 4) ? (4 * t) : (4 * (t - 4) + 2)) + e;
}

// ============================================================
// Weight packer (coalesced reads) + init (R15 version).
// ============================================================
__global__ void __launch_bounds__(256) pack_weights_kernel(
    const float* __restrict__ qW1, const float* __restrict__ kW1, const float* __restrict__ vW1,
    const float* __restrict__ qW2, const float* __restrict__ kW2, const float* __restrict__ vW2)
{
    const int i = blockIdx.x * 256 + threadIdx.x;
    if (i == 0) g_count = 0u;
    if (i < B_ * D_) g_max[i] = 0u;

    if (i < 3 * 8192) {
        const int n   = i & 255;
        const int r2  = i >> 8;
        const int p   = r2 & 1;
        const int tig = (r2 >> 1) & 3;
        const int ks  = (r2 >> 3) & 3;
        const int mlp = r2 >> 5;
        const float* W = (mlp == 0) ? qW1 : (mlp == 1) ? kW1 : vW1;
        const int kp = 8 * ks + tig + (p ? 4 : 0);
        const int out = ((mlp * 256 + n) * 4 + ks) * 8 + tig * 2 + p;
        g_w1p[out] = pkhf(W[(2 * kp) * HID_ + n], W[(2 * kp + 1) * HID_ + n]);
    }
    if (i < 3 * 16384) {
        const int n   = i & 127;
        const int r2  = i >> 7;
        const int p   = r2 & 1;
        const int tig = (r2 >> 1) & 3;
        const int ks  = (r2 >> 3) & 15;
        const int mlp = r2 >> 7;
        const float* W = (mlp == 0) ? qW2 : (mlp == 1) ? kW2 : vW2;
        const int kp = 8 * ks + tig + (p ? 4 : 0);
        const int out = ((mlp * 128 + n) * 16 + ks) * 8 + tig * 2 + p;
        g_w2p[out] = pkhf(W[(2 * kp) * D_ + n], W[(2 * kp + 1) * D_ + n]);
    }
}

// ============================================================
// Tensor-core MLP (R11 version): block = 64 tokens, 8 warps.
// grid (8192/64, 3). Weight fetch = LDG.64 (pair-adjacent).
// ============================================================
__global__ void __launch_bounds__(256) mlp_mma_kernel(
    const float* __restrict__ x,
    const float* __restrict__ qb1, const float* __restrict__ qb2,
    const float* __restrict__ kb1, const float* __restrict__ kb2,
    const float* __restrict__ vb1, const float* __restrict__ vb2)
{
    __shared__ u32 xs[64][36];
    __shared__ u32 hsm[64][132];

    const int tid  = threadIdx.x;
    const int lane = tid & 31;
    const int warp = tid >> 5;
    const int gID  = lane >> 2;
    const int tig  = lane & 3;
    const int mlp  = blockIdx.y;
    const int tok0 = blockIdx.x * 64;

    const float* b1v = (mlp == 0) ? qb1 : (mlp == 1) ? kb1 : vb1;
    const float* b2v = (mlp == 0) ? qb2 : (mlp == 1) ? kb2 : vb2;

    {
        const float4* xg = (const float4*)(x + (size_t)tok0 * F_);
        #pragma unroll
        for (int r = 0; r < 4; r++) {
            const int g   = tid + r * 256;
            const int tok = g >> 4;
            const int f4  = g & 15;
            const float4 v = xg[g];
            xs[tok][f4 * 2 + 0] = pkhf(v.x, v.y);
            xs[tok][f4 * 2 + 1] = pkhf(v.z, v.w);
        }
    }
    __syncthreads();

    const int tg = warp >> 1;
    const int nh = warp & 1;
    const int ra = tg * 16 + gID;

    float acc[16][4];
    #pragma unroll
    for (int j = 0; j < 16; j++)
        #pragma unroll
        for (int e = 0; e < 4; e++) acc[j][e] = 0.f;

    {
        const u32* wb = g_w1p + mlp * 8192;
        #pragma unroll
        for (int ks = 0; ks < 4; ks++) {
            u32 a[4];
            a[0] = xs[ra][8 * ks + tig];
            a[1] = xs[ra + 8][8 * ks + tig];
            a[2] = xs[ra][8 * ks + tig + 4];
            a[3] = xs[ra + 8][8 * ks + tig + 4];
            #pragma unroll
            for (int j = 0; j < 16; j++) {
                const int n = nh * 128 + j * 8 + gID;
                const uint2 w = __ldg((const uint2*)(wb + n * 32 + ks * 8 + tig * 2));
                mma_f16(acc[j], a, w.x, w.y);
            }
        }
    }

    #pragma unroll
    for (int j = 0; j < 16; j++) {
        const int c0 = nh * 128 + j * 8 + 2 * tig;
        const float bb0 = b1v[c0], bb1 = b1v[c0 + 1];
        float e0 = acc[j][0] + bb0, e1 = acc[j][1] + bb1;
        float e2 = acc[j][2] + bb0, e3 = acc[j][3] + bb1;
        e0 = (e0 > 0.f) ? e0 : (__expf(e0) - 1.f);
        e1 = (e1 > 0.f) ? e1 : (__expf(e1) - 1.f);
        e2 = (e2 > 0.f) ? e2 : (__expf(e2) - 1.f);
        e3 = (e3 > 0.f) ? e3 : (__expf(e3) - 1.f);
        hsm[ra][nh * 64 + 4 * j + tig]     = pkhf(e0, e1);
        hsm[ra + 8][nh * 64 + 4 * j + tig] = pkhf(e2, e3);
    }
    __syncthreads();

    float out[8][4];
    #pragma unroll
    for (int j = 0; j < 8; j++)
        #pragma unroll
        for (int e = 0; e < 4; e++) out[j][e] = 0.f;

    {
        const u32* wb = g_w2p + mlp * 16384;
        #pragma unroll
        for (int ks = 0; ks < 16; ks++) {
            u32 a[4];
            a[0] = hsm[ra][8 * ks + tig];
            a[1] = hsm[ra + 8][8 * ks + tig];
            a[2] = hsm[ra][8 * ks + tig + 4];
            a[3] = hsm[ra + 8][8 * ks + tig + 4];
            #pragma unroll
            for (int j = 0; j < 8; j++) {
                const int n = nh * 64 + j * 8 + gID;
                const uint2 w = __ldg((const uint2*)(wb + n * 128 + ks * 8 + tig * 2));
                mma_f16(out[j], a, w.x, w.y);
            }
        }
    }

    const float qsc = (mlp == 0) ? 0.25f * 1.4426950408889634f : 1.0f;
    #pragma unroll
    for (int j = 0; j < 8; j++) {
        const int c0 = nh * 64 + j * 8 + 2 * tig;
        const float bb0 = b2v[c0], bb1 = b2v[c0 + 1];
        const float v00 = (out[j][0] + bb0) * qsc;
        const float v01 = (out[j][1] + bb1) * qsc;
        const float v10 = (out[j][2] + bb0) * qsc;
        const float v11 = (out[j][3] + bb1) * qsc;
        const u32 pr = pkhf(v00, v01);
        const u32 ps = pkhf(v10, v11);

        const int h   = c0 >> 4;
        const int dk0 = c0 & 15;
        const int tokA = tok0 + ra;
        const int bA = tokA >> 11, sA = tokA & (S_ - 1);
        const int tokB = tokA + 8;
        const int bB = tokB >> 11, sB = tokB & (S_ - 1);
        const int bhA = bA * H_ + h, bhB = bB * H_ + h;

        if (mlp < 2) {
            u16* base = (mlp == 0) ? g_qs : g_ks;
            const int php = dk_pair_phys(dk0 >> 1);
            *(u32*)&base[((size_t)bhA * S_ + sA) * 16 + php * 2] = pr;
            *(u32*)&base[((size_t)bhB * S_ + sB) * 16 + php * 2] = ps;
        } else {
            const int spA = (sA & ~15) | v_key_phys(sA & 15);
            const int spB = (sB & ~15) | v_key_phys(sB & 15);
            g_vt[((size_t)bhA * 16 + dk0) * S_ + spA]     = (u16)(pr & 0xFFFF);
            g_vt[((size_t)bhA * 16 + dk0 + 1) * S_ + spA] = (u16)(pr >> 16);
            g_vt[((size_t)bhB * 16 + dk0) * S_ + spB]     = (u16)(ps & 0xFFFF);
            g_vt[((size_t)bhB * 16 + dk0 + 1) * S_ + spB] = (u16)(ps >> 16);
        }
    }
}

#define QSTR 16
#define VSTR 144
#define ONES 0x3C003C00u
#define QT   128                        // queries per attention block (2 sets of 64)
#define NBLK ((S_ / QT) * B_ * H_)      // 512
#define NT   (S_ / 128)

// one 64-query set against the current tile (half): QK -> exp2 -> PV + lsum
__device__ __forceinline__ void attn_set(
    const u32 qa[4], float o0[4], float o1[4], float lsv[4],
    const u16 (*KsB)[QSTR], const u16 (*VtB)[VSTR],
    int half, int gID, int tig)
{
    u32 pa[8], pb[8];
    #pragma unroll
    for (int j = 0; j < 8; j++) {
        const int kn = half * 64 + j * 8 + gID;
        const uint2 bb = *(const uint2*)&KsB[kn][4 * tig];
        u32 d0, d1;
        mma_f16d(d0, d1, qa, bb.x, bb.y);
        pa[j] = ex2h2(d0);
        pb[j] = ex2h2(d1);
    }
    #pragma unroll
    for (int ks = 0; ks < 4; ks++) {
        const u32 A[4] = {pa[2 * ks], pb[2 * ks], pa[2 * ks + 1], pb[2 * ks + 1]};
        const int kb2 = half * 64 + ks * 16 + 4 * tig;
        {
            const uint2 vv = *(const uint2*)&VtB[gID][kb2];
            mma_f16(o0, A, vv.x, vv.y);
        }
        {
            const uint2 vv = *(const uint2*)&VtB[8 + gID][kb2];
            mma_f16(o1, A, vv.x, vv.y);
        }
        mma_f16(lsv, A, ONES, ONES);
    }
}

// ============================================================
// fp16 mma.sync flash attention; 128 q/block as TWO 64-query sets
// per K/V tile; cp.async triple-buffered; 128 threads.
// ============================================================
__global__ void __launch_bounds__(128) attn_mma_kernel(float* __restrict__ outp)
{
    __shared__ __align__(16) u16 Qs[128][QSTR];         // 4096 B
    __shared__ __align__(16) u16 Ks[3][128][QSTR];      // 12288 B
    __shared__ __align__(16) u16 Vt[3][16][VSTR];       // 13824 B
    __shared__ float red[64 * 17];                      // 4352 B
    __shared__ unsigned s_last;

    const int tid  = threadIdx.x;
    const int lane = tid & 31;
    const int warp = tid >> 5;
    const int gID  = lane >> 2;
    const int tig  = lane & 3;
    const int bh   = blockIdx.y;
    const int q0   = blockIdx.x * QT;

    #pragma unroll
    for (int cc = 0; cc < 2; cc++) {
        const int c    = tid + cc * 128;
        const int r    = c >> 1;
        const int part = c & 1;
        const uint4 v = *(const uint4*)&g_qs[((size_t)bh * S_ + q0 + r) * 16 + part * 8];
        *(uint4*)&Qs[r][part * 8] = v;
    }
    __syncthreads();

    u32 qa[4], qb[4];
    const int ra = warp * 16 + gID;
    {
        const uint2 a0 = *(const uint2*)&Qs[ra][4 * tig];
        const uint2 a1 = *(const uint2*)&Qs[ra + 8][4 * tig];
        qa[0] = a0.x; qa[2] = a0.y;
        qa[1] = a1.x; qa[3] = a1.y;
        const uint2 b0 = *(const uint2*)&Qs[64 + ra][4 * tig];
        const uint2 b1 = *(const uint2*)&Qs[64 + ra + 8][4 * tig];
        qb[0] = b0.x; qb[2] = b0.y;
        qb[1] = b1.x; qb[3] = b1.y;
    }

    // per-thread cp.async coordinates
    const int kr0 = tid >> 1;
    const int kp0 = (tid & 1) * 8;
    const int kr1 = (tid + 128) >> 1;
    const int kp1 = ((tid + 128) & 1) * 8;
    const int vd0 = tid >> 4;
    const int vo0 = (tid & 15) * 8;
    const int vd1 = (tid + 128) >> 4;
    const int vo1 = ((tid + 128) & 15) * 8;
    const u16* kgb = g_ks + (size_t)bh * S_ * 16;
    const u16* vgb = g_vt + (size_t)bh * 16 * S_;

    const u32 sKa0 = (u32)__cvta_generic_to_shared(&Ks[0][kr0][kp0]);
    const u32 sKa1 = (u32)__cvta_generic_to_shared(&Ks[0][kr1][kp1]);
    const u32 sVa0 = (u32)__cvta_generic_to_shared(&Vt[0][vd0][vo0]);
    const u32 sVa1 = (u32)__cvta_generic_to_shared(&Vt[0][vd1][vo1]);
    const u32 kBufB = 128 * QSTR * 2;
    const u32 vBufB = 16 * VSTR * 2;

    {
        cpa16(sKa0, &kgb[(size_t)kr0 * 16 + kp0]);
        cpa16(sKa1, &kgb[(size_t)kr1 * 16 + kp1]);
        cpa16(sVa0, &vgb[(size_t)vd0 * S_ + vo0]);
        cpa16(sVa1, &vgb[(size_t)vd1 * S_ + vo1]);
        cpa_commit();
    }

    float out0[4] = {0.f, 0.f, 0.f, 0.f};
    float out1[4] = {0.f, 0.f, 0.f, 0.f};
    float out2[4] = {0.f, 0.f, 0.f, 0.f};
    float out3[4] = {0.f, 0.f, 0.f, 0.f};
    float ls[4]   = {0.f, 0.f, 0.f, 0.f};
    float lsB[4]  = {0.f, 0.f, 0.f, 0.f};

    int buf = 0;
    for (int t = 0; t < NT; t++) {
        if (t + 1 < NT) {
            const int nb = (buf == 2) ? 0 : buf + 1;
            const int tt = (t + 1) * 128;
            cpa16(sKa0 + nb * kBufB, &kgb[(size_t)(tt + kr0) * 16 + kp0]);
            cpa16(sKa1 + nb * kBufB, &kgb[(size_t)(tt + kr1) * 16 + kp1]);
            cpa16(sVa0 + nb * vBufB, &vgb[(size_t)vd0 * S_ + tt + vo0]);
            cpa16(sVa1 + nb * vBufB, &vgb[(size_t)vd1 * S_ + tt + vo1]);
            cpa_commit();
            cpa_wait<1>();
        } else {
            cpa_wait<0>();
        }
        __syncthreads();

        #pragma unroll
        for (int half = 0; half < 2; half++) {
            attn_set(qa, out0, out1, ls,  Ks[buf], Vt[buf], half, gID, tig);
            attn_set(qb, out2, out3, lsB, Ks[buf], Vt[buf], half, gID, tig);
        }
        buf = (buf == 2) ? 0 : buf + 1;
    }

    const float i0 = 1.f / ls[0];
    const float i1 = 1.f / ls[2];
    const float i2 = 1.f / lsB[0];
    const float i3 = 1.f / lsB[2];

    __syncthreads();
    {
        // merge the two query sets with fmax before the block reduction
        const int c0 = 2 * tig;
        red[ra * 17 + c0 + 0]       = fmaxf(out0[0] * i0, out2[0] * i2);
        red[ra * 17 + c0 + 1]       = fmaxf(out0[1] * i0, out2[1] * i2);
        red[(ra + 8) * 17 + c0 + 0] = fmaxf(out0[2] * i1, out2[2] * i3);
        red[(ra + 8) * 17 + c0 + 1] = fmaxf(out0[3] * i1, out2[3] * i3);
        red[ra * 17 + 8 + c0 + 0]       = fmaxf(out1[0] * i0, out3[0] * i2);
        red[ra * 17 + 8 + c0 + 1]       = fmaxf(out1[1] * i0, out3[1] * i2);
        red[(ra + 8) * 17 + 8 + c0 + 0] = fmaxf(out1[2] * i1, out3[2] * i3);
        red[(ra + 8) * 17 + 8 + c0 + 1] = fmaxf(out1[3] * i1, out3[3] * i3);
    }
    __syncthreads();

    float* part = (float*)&Qs[0][0];
    {
        const int c  = tid & 15;
        const int r0 = tid >> 4;
        float m = red[r0 * 17 + c];
        #pragma unroll
        for (int i = 1; i < 8; i++)
            m = fmaxf(m, red[(r0 + 8 * i) * 17 + c]);
        part[r0 * 16 + c] = m;
    }
    __syncthreads();
    if (tid < 16) {
        float m = part[tid];
        #pragma unroll
        for (int r = 1; r < 8; r++)
            m = fmaxf(m, part[r * 16 + tid]);
        const int b = bh >> 3, h = bh & 7;
        atomicMax(&g_max[b * D_ + h * DK_ + tid], fkey(m));
    }

    // ---- last block writes the output ----
    __threadfence();
    __syncthreads();
    if (tid == 0) s_last = atomicAdd(&g_count, 1u);
    __syncthreads();
    if (s_last == NBLK - 1) {
        #pragma unroll
        for (int r = 0; r < 4; r++) {
            const int i = tid + r * 128;
            outp[i] = ikey(atomicOr(&g_max[i], 0u));
        }
    }
}

extern "C" void kernel_launch(void* const* d_in, const int* in_sizes, int n_in,
                              void* d_out, int out_size)
{
    const float* x   = (const float*)d_in[0];
    const float* qW1 = (const float*)d_in[1];
    const float* qb1 = (const float*)d_in[2];
    const float* qW2 = (const float*)d_in[3];
    const float* qb2 = (const float*)d_in[4];
    const float* kW1 = (const float*)d_in[5];
    const float* kb1 = (const float*)d_in[6];
    const float* kW2 = (const float*)d_in[7];
    const float* kb2 = (const float*)d_in[8];
    const float* vW1 = (const float*)d_in[9];
    const float* vb1 = (const float*)d_in[10];
    const float* vW2 = (const float*)d_in[11];
    const float* vb2 = (const float*)d_in[12];

    pack_weights_kernel<<<192, 256>>>(qW1, kW1, vW1, qW2, kW2, vW2);

    dim3 gmlp(B_ * S_ / 64, 3);
    mlp_mma_kernel<<<gmlp, 256>>>(x, qb1, qb2, kb1, kb2, vb1, vb2);

    dim3 gatt(S_ / QT, B_ * H_);
    attn_mma_kernel<<<gatt, 128>>>((float*)d_out);
}